// round 6
// baseline (speedup 1.0000x reference)
#include <cuda_runtime.h>
#include <cuda_bf16.h>

typedef unsigned long long ull;

#define GMM_M   64
#define GMM_D   16
#define GMM_KP  8      // 16 dims = 8 f32x2 pairs
#define TPB     128
#define PPB     TPB    // PPT = 1
#define NBLK    1036   // 148 SMs x 7 blocks

// staging (written by precompute kernel), then memcpy'd into __constant__
__device__ float4   g_P[GMM_M * GMM_KP];  // {A2k,A2k+1,B2k,B2k+1}, log2e-folded
__device__ float    g_C[GMM_M];
__device__ float    g_part[NBLK];
__device__ unsigned g_count = 0;

// warp-uniform params on the constant port (off the L1 crossbar)
__constant__ float4 cP[GMM_M * GMM_KP];   // 8 KB
__constant__ float  cC[GMM_M];            // 256 B

__device__ __forceinline__ ull pk2(float lo, float hi) {
    ull r; asm("mov.b64 %0, {%1, %2};" : "=l"(r) : "f"(lo), "f"(hi)); return r;
}
__device__ __forceinline__ void upk2(ull v, float &lo, float &hi) {
    asm("mov.b64 {%0, %1}, %2;" : "=f"(lo), "=f"(hi) : "l"(v));
}
__device__ __forceinline__ ull fma2(ull a, ull b, ull c) {
    ull r; asm("fma.rn.f32x2 %0, %1, %2, %3;" : "=l"(r) : "l"(a), "l"(b), "l"(c)); return r;
}
__device__ __forceinline__ float ex2f(float x) {
    float r; asm("ex2.approx.f32 %0, %1;" : "=f"(r) : "f"(x)); return r;
}

// ---------- kernel 1: parameter precompute (log2e folded) ----------
__global__ void __launch_bounds__(1024)
gmm_precompute(const float* __restrict__ wghts,
               const float* __restrict__ means,
               const float* __restrict__ dcovs) {
    __shared__ float sAf[GMM_M][GMM_D];
    __shared__ float sBf[GMM_M][GMM_D];
    const int tid = threadIdx.x;
    const int m = tid >> 4;
    const int d = tid & 15;
    const float LOG2E = 1.4426950408889634f;

    const float dc   = dcovs[m * GMM_D + d];
    const float mu   = means[m * GMM_D + d];
    const float prec = 1.0f / dc;
    sAf[m][d] = -0.5f * prec * LOG2E;
    sBf[m][d] = prec * mu * LOG2E;

    float cpart = (-0.5f * prec * mu * mu - 0.5f * __logf(dc)) * LOG2E;
    #pragma unroll
    for (int o = 8; o > 0; o >>= 1)
        cpart += __shfl_down_sync(0xffffffffu, cpart, o, 16);
    if (d == 0)
        g_C[m] = cpart + (__logf(wghts[m]) - 8.0f * __logf(6.283185307f)) * LOG2E;

    __syncthreads();
    if (tid < GMM_M * GMM_KP) {
        const int pm = tid >> 3;
        const int k  = tid & 7;
        g_P[tid] = make_float4(sAf[pm][2*k], sAf[pm][2*k+1],
                               sBf[pm][2*k], sBf[pm][2*k+1]);
    }
}

// ---------- kernel 2: main GMM E-step (params via constant port) ----------
__global__ void __launch_bounds__(TPB, 7)
gmm_main(const float* __restrict__ data,
         const float* __restrict__ means,
         float* __restrict__ out,
         int T, int ntiles, float invT) {
    __shared__ ulonglong2 sMu[GMM_M * 4];     // mu pairs (only non-uniform-path param)
    __shared__ float      sStage[TPB * 17];   // pitch-17 transpose buffer
    __shared__ float      sRed[TPB];
    __shared__ bool       sLast;

    const int tid = threadIdx.x;
    {
        const float4* gm = (const float4*)means;
        float4*       dm = (float4*)sMu;
        for (int i = tid; i < GMM_M * 4; i += TPB) dm[i] = gm[i];
    }
    __syncthreads();

    float llsum = 0.0f;

    for (int tile = blockIdx.x; tile < ntiles; tile += gridDim.x) {
        const int base = tile * PPB;
        const int t    = base + tid;
        const bool valid = (t < T);

        ull x[GMM_KP], num[GMM_KP];
        float like = 0.0f;

        if (valid) {
            const float4* dp4 = (const float4*)(data + (size_t)t * GMM_D);
            #pragma unroll
            for (int q = 0; q < 4; q++) {
                const float4 f = dp4[q];
                x[2*q]   = pk2(f.x, f.y);
                x[2*q+1] = pk2(f.z, f.w);
            }
        } else {
            #pragma unroll
            for (int k = 0; k < GMM_KP; k++) x[k] = 0ULL;
        }
        #pragma unroll
        for (int k = 0; k < GMM_KP; k++) num[k] = 0ULL;

        #pragma unroll 2
        for (int m = 0; m < GMM_M; m++) {
            // c folded into accumulator init: acc = (c, 0)
            ull acc = pk2(cC[m], 0.0f);

            #pragma unroll
            for (int k = 0; k < GMM_KP; k++) {
                // uniform address -> constant port (LDC/LDCU), not L1 crossbar
                const ulonglong2 ab = *(const ulonglong2*)&cP[m * GMM_KP + k];
                const ull tt = fma2(ab.x, x[k], ab.y);
                acc = fma2(tt, x[k], acc);
            }

            float lo, hi;
            upk2(acc, lo, hi);
            const float p = ex2f(lo + hi);
            like += p;
            const ull pb = pk2(p, p);

            #pragma unroll
            for (int kk = 0; kk < 4; kk++) {
                const ulonglong2 mm = sMu[m * 4 + kk];
                num[2*kk]   = fma2(pb, mm.x, num[2*kk]);
                num[2*kk+1] = fma2(pb, mm.y, num[2*kk+1]);
            }
        }

        const float inv = valid ? __fdividef(1.0f, like) : 0.0f;
        if (valid) llsum += __logf(like);

        // epilogue: SMEM transpose -> coalesced STG.32 (out+1 only 4B-aligned)
        #pragma unroll
        for (int k = 0; k < GMM_KP; k++) {
            float f0, f1;
            upk2(num[k], f0, f1);
            sStage[tid * 17 + 2*k]     = f0 * inv;
            sStage[tid * 17 + 2*k + 1] = f1 * inv;
        }
        __syncthreads();

        float* op = out + 1 + (size_t)base * GMM_D;
        const int limit = min(TPB, T - base) * GMM_D;
        for (int i = tid; i < limit; i += TPB)
            op[i] = sStage[(i >> 4) * 17 + (i & 15)];
        __syncthreads();
    }

    // deterministic block reduction of log-likes
    sRed[tid] = llsum;
    __syncthreads();
    #pragma unroll
    for (int s = TPB / 2; s > 0; s >>= 1) {
        if (tid < s) sRed[tid] += sRed[tid + s];
        __syncthreads();
    }
    if (tid == 0) {
        g_part[blockIdx.x] = sRed[0];
        __threadfence();
        unsigned old = atomicAdd(&g_count, 1u);
        sLast = (old == (unsigned)(gridDim.x - 1));
    }
    __syncthreads();

    if (sLast) {
        __threadfence();
        float acc2 = 0.0f;
        for (int i = tid; i < (int)gridDim.x; i += TPB) acc2 += g_part[i];
        sRed[tid] = acc2;
        __syncthreads();
        #pragma unroll
        for (int s = TPB / 2; s > 0; s >>= 1) {
            if (tid < s) sRed[tid] += sRed[tid + s];
            __syncthreads();
        }
        if (tid == 0) {
            out[0] = sRed[0] * invT;
            g_count = 0;
        }
    }
}

extern "C" void kernel_launch(void* const* d_in, const int* in_sizes, int n_in,
                              void* d_out, int out_size) {
    const float* data  = (const float*)d_in[0];
    const float* wghts = (const float*)d_in[1];
    const float* means = (const float*)d_in[2];
    const float* dcovs = (const float*)d_in[3];
    float* out = (float*)d_out;

    const int T = in_sizes[0] / GMM_D;
    const int ntiles = (T + PPB - 1) / PPB;
    const int grid = (ntiles < NBLK) ? ntiles : NBLK;

    gmm_precompute<<<1, 1024>>>(wghts, means, dcovs);

    // stage -> constant (device-to-device async copies: graph-capturable)
    void *srcP = nullptr, *srcC = nullptr;
    cudaGetSymbolAddress(&srcP, g_P);
    cudaGetSymbolAddress(&srcC, g_C);
    cudaMemcpyToSymbolAsync(cP, srcP, sizeof(float4) * GMM_M * GMM_KP, 0,
                            cudaMemcpyDeviceToDevice, 0);
    cudaMemcpyToSymbolAsync(cC, srcC, sizeof(float) * GMM_M, 0,
                            cudaMemcpyDeviceToDevice, 0);

    gmm_main<<<grid, TPB>>>(data, means, out, T, ntiles, 1.0f / (float)T);
}

// round 7
// speedup vs baseline: 1.9275x; 1.9275x over previous
#include <cuda_runtime.h>
#include <cuda_bf16.h>

typedef unsigned long long ull;

#define GMM_M   64
#define GMM_D   16
#define GMM_KP  8      // 16 dims = 8 f32x2 pairs
#define TPB     128
#define PPT     2
#define PPB     (TPB*PPT)

__device__ float4   g_P[GMM_M * GMM_KP];  // {A2k,A2k+1,B2k,B2k+1}, log2e-folded
__device__ float    g_C[GMM_M];           // log2e-folded constant
__device__ float    g_part[8192];
__device__ unsigned g_count = 0;

__device__ __forceinline__ ull pk2(float lo, float hi) {
    ull r; asm("mov.b64 %0, {%1, %2};" : "=l"(r) : "f"(lo), "f"(hi)); return r;
}
__device__ __forceinline__ void upk2(ull v, float &lo, float &hi) {
    asm("mov.b64 {%0, %1}, %2;" : "=f"(lo), "=f"(hi) : "l"(v));
}
__device__ __forceinline__ ull fma2(ull a, ull b, ull c) {
    ull r; asm("fma.rn.f32x2 %0, %1, %2, %3;" : "=l"(r) : "l"(a), "l"(b), "l"(c)); return r;
}
__device__ __forceinline__ float ex2f(float x) {
    float r; asm("ex2.approx.f32 %0, %1;" : "=f"(r) : "f"(x)); return r;
}

// ---------- kernel 1: parameter precompute (log2e folded) ----------
__global__ void __launch_bounds__(1024)
gmm_precompute(const float* __restrict__ wghts,
               const float* __restrict__ means,
               const float* __restrict__ dcovs) {
    __shared__ float sAf[GMM_M][GMM_D];
    __shared__ float sBf[GMM_M][GMM_D];
    const int tid = threadIdx.x;
    const int m = tid >> 4;
    const int d = tid & 15;
    const float LOG2E = 1.4426950408889634f;

    const float dc   = dcovs[m * GMM_D + d];
    const float mu   = means[m * GMM_D + d];
    const float prec = 1.0f / dc;
    sAf[m][d] = -0.5f * prec * LOG2E;
    sBf[m][d] = prec * mu * LOG2E;

    float cpart = (-0.5f * prec * mu * mu - 0.5f * __logf(dc)) * LOG2E;
    #pragma unroll
    for (int o = 8; o > 0; o >>= 1)
        cpart += __shfl_down_sync(0xffffffffu, cpart, o, 16);
    if (d == 0)
        g_C[m] = cpart + (__logf(wghts[m]) - 8.0f * __logf(6.283185307f)) * LOG2E;

    __syncthreads();
    if (tid < GMM_M * GMM_KP) {
        const int pm = tid >> 3;
        const int k  = tid & 7;
        g_P[tid] = make_float4(sAf[pm][2*k], sAf[pm][2*k+1],
                               sBf[pm][2*k], sBf[pm][2*k+1]);
    }
}

// ---------- kernel 2: main GMM E-step (non-persistent, HW backfill) ----------
__global__ void __launch_bounds__(TPB, 5)
gmm_main(const float* __restrict__ data,
         const float* __restrict__ means,
         float* __restrict__ out,
         int T, float invT) {
    __shared__ ulonglong2 sP[GMM_M * GMM_KP];
    __shared__ ulonglong2 sMu[GMM_M * 4];
    __shared__ float      sC[GMM_M];
    __shared__ float      sStage[TPB * 17];   // pitch-17 transpose buffer
    __shared__ float      sRed[TPB];
    __shared__ bool       sLast;

    const int tid = threadIdx.x;
    {
        const float4* gp = (const float4*)g_P;
        float4*       dp = (float4*)sP;
        for (int i = tid; i < GMM_M * GMM_KP; i += TPB) dp[i] = gp[i];
        const float4* gm = (const float4*)means;
        float4*       dm = (float4*)sMu;
        for (int i = tid; i < GMM_M * 4; i += TPB) dm[i] = gm[i];
        if (tid < GMM_M) sC[tid] = g_C[tid];
    }
    __syncthreads();

    const int base = blockIdx.x * PPB;

    ull x[PPT][GMM_KP], num[PPT][GMM_KP];
    float like[PPT];

    #pragma unroll
    for (int j = 0; j < PPT; j++) {
        like[j] = 0.0f;
        const int t = base + tid + j * TPB;
        if (t < T) {
            const float4* dp4 = (const float4*)(data + (size_t)t * GMM_D);
            #pragma unroll
            for (int q = 0; q < 4; q++) {
                const float4 f = dp4[q];
                x[j][2*q]   = pk2(f.x, f.y);
                x[j][2*q+1] = pk2(f.z, f.w);
            }
        } else {
            #pragma unroll
            for (int k = 0; k < GMM_KP; k++) x[j][k] = 0ULL;
        }
        #pragma unroll
        for (int k = 0; k < GMM_KP; k++) num[j][k] = 0ULL;
    }

    #pragma unroll 2
    for (int m = 0; m < GMM_M; m++) {
        ull acc[PPT];
        #pragma unroll
        for (int j = 0; j < PPT; j++) acc[j] = pk2(sC[m], 0.0f);

        #pragma unroll
        for (int k = 0; k < GMM_KP; k++) {
            const ulonglong2 ab = sP[m * GMM_KP + k];   // LDS.128 broadcast
            #pragma unroll
            for (int j = 0; j < PPT; j++) {
                const ull tt = fma2(ab.x, x[j][k], ab.y);
                acc[j] = fma2(tt, x[j][k], acc[j]);
            }
        }

        ull pb[PPT];
        #pragma unroll
        for (int j = 0; j < PPT; j++) {
            float lo, hi;
            upk2(acc[j], lo, hi);
            const float p = ex2f(lo + hi);
            like[j] += p;
            pb[j] = pk2(p, p);
        }

        #pragma unroll
        for (int kk = 0; kk < 4; kk++) {
            const ulonglong2 mm = sMu[m * 4 + kk];
            #pragma unroll
            for (int j = 0; j < PPT; j++) {
                num[j][2*kk]   = fma2(pb[j], mm.x, num[j][2*kk]);
                num[j][2*kk+1] = fma2(pb[j], mm.y, num[j][2*kk+1]);
            }
        }
    }

    float llsum = 0.0f;

    // epilogue: SMEM transpose -> coalesced STG.32 (out+1 only 4B-aligned)
    #pragma unroll
    for (int j = 0; j < PPT; j++) {
        const int tj = base + tid + j * TPB;
        const bool valid = (tj < T);
        const float inv = valid ? __fdividef(1.0f, like[j]) : 0.0f;
        if (valid) llsum += __logf(like[j]);

        #pragma unroll
        for (int k = 0; k < GMM_KP; k++) {
            float f0, f1;
            upk2(num[j][k], f0, f1);
            sStage[tid * 17 + 2*k]     = f0 * inv;
            sStage[tid * 17 + 2*k + 1] = f1 * inv;
        }
        __syncthreads();

        float* op = out + 1 + (size_t)(base + j * TPB) * GMM_D;
        const int limit = min(TPB, T - (base + j * TPB)) * GMM_D;
        for (int i = tid; i < limit; i += TPB)
            op[i] = sStage[(i >> 4) * 17 + (i & 15)];
        __syncthreads();
    }

    // deterministic block reduction of log-likes
    sRed[tid] = llsum;
    __syncthreads();
    #pragma unroll
    for (int s = TPB / 2; s > 0; s >>= 1) {
        if (tid < s) sRed[tid] += sRed[tid + s];
        __syncthreads();
    }
    if (tid == 0) {
        g_part[blockIdx.x] = sRed[0];
        __threadfence();
        unsigned old = atomicAdd(&g_count, 1u);
        sLast = (old == (unsigned)(gridDim.x - 1));
    }
    __syncthreads();

    if (sLast) {
        __threadfence();
        float acc2 = 0.0f;
        for (int i = tid; i < (int)gridDim.x; i += TPB) acc2 += g_part[i];
        sRed[tid] = acc2;
        __syncthreads();
        #pragma unroll
        for (int s = TPB / 2; s > 0; s >>= 1) {
            if (tid < s) sRed[tid] += sRed[tid + s];
            __syncthreads();
        }
        if (tid == 0) {
            out[0] = sRed[0] * invT;
            g_count = 0;
        }
    }
}

extern "C" void kernel_launch(void* const* d_in, const int* in_sizes, int n_in,
                              void* d_out, int out_size) {
    const float* data  = (const float*)d_in[0];
    const float* wghts = (const float*)d_in[1];
    const float* means = (const float*)d_in[2];
    const float* dcovs = (const float*)d_in[3];
    float* out = (float*)d_out;

    const int T = in_sizes[0] / GMM_D;
    const int grid = (T + PPB - 1) / PPB;   // non-persistent: HW backfills

    gmm_precompute<<<1, 1024>>>(wghts, means, dcovs);
    gmm_main<<<grid, TPB>>>(data, means, out, T, 1.0f / (float)T);
}